// round 1
// baseline (speedup 1.0000x reference)
#include <cuda_runtime.h>
#include <math.h>

// Problem constants (B=2, S=2048, D=1024, H=16, DPH=64)
#define BATCH 2
#define SEQ   2048
#define DIM   1024
#define HEADS 16
#define DPH   64
#define MROWS (BATCH * SEQ)   // 4096

// Scratch (allocation-free rule: __device__ globals)
__device__ float g_q[BATCH * SEQ * DIM];
__device__ float g_k[BATCH * SEQ * DIM];
__device__ float g_v[BATCH * SEQ * DIM];
__device__ float g_ctx[BATCH * SEQ * DIM];

// ---------------------------------------------------------------------------
// C[M,N] = (A[M,K] @ W[K,N] + bias[N]) * alpha
// Classic 128x128x8 register-blocked SGEMM, 256 threads, 8x8 per thread.
// M,N,K all multiples of tile sizes here (4096/1024/1024) -> no bounds checks.
// ---------------------------------------------------------------------------
__global__ void __launch_bounds__(256) sgemm_bias(
    const float* __restrict__ A, const float* __restrict__ W,
    const float* __restrict__ bias, float* __restrict__ C,
    int M, int N, int K, float alpha)
{
    __shared__ float As[8][136];   // transposed A tile, padded stride
    __shared__ float Ws[8][128];

    const int tid = threadIdx.x;
    const int bx = blockIdx.x, by = blockIdx.y;
    const int tx = tid & 15, ty = tid >> 4;

    // A tile load mapping: 128 rows x 8 k, float4 along k
    const int arow = tid >> 1;
    const int acol = (tid & 1) * 4;
    // W tile load mapping: 8 k-rows x 128 cols, float4 along cols
    const int wrow = tid >> 5;
    const int wcol = (tid & 31) * 4;

    const float* Ablk = A + (size_t)(by * 128) * K;
    const float* Wblk = W + bx * 128;

    float acc[8][8];
#pragma unroll
    for (int i = 0; i < 8; i++)
#pragma unroll
        for (int j = 0; j < 8; j++) acc[i][j] = 0.f;

    for (int kt = 0; kt < K; kt += 8) {
        float4 av = *(const float4*)(Ablk + (size_t)arow * K + kt + acol);
        As[acol + 0][arow] = av.x;
        As[acol + 1][arow] = av.y;
        As[acol + 2][arow] = av.z;
        As[acol + 3][arow] = av.w;
        *(float4*)&Ws[wrow][wcol] =
            *(const float4*)(Wblk + (size_t)(kt + wrow) * N + wcol);
        __syncthreads();

#pragma unroll
        for (int k = 0; k < 8; k++) {
            float a[8], bb[8];
            *(float4*)&a[0]  = *(const float4*)&As[k][ty * 8];
            *(float4*)&a[4]  = *(const float4*)&As[k][ty * 8 + 4];
            *(float4*)&bb[0] = *(const float4*)&Ws[k][tx * 8];
            *(float4*)&bb[4] = *(const float4*)&Ws[k][tx * 8 + 4];
#pragma unroll
            for (int i = 0; i < 8; i++)
#pragma unroll
                for (int j = 0; j < 8; j++)
                    acc[i][j] = fmaf(a[i], bb[j], acc[i][j]);
        }
        __syncthreads();
    }

    const int crow0 = by * 128 + ty * 8;
    const int ccol0 = bx * 128 + tx * 8;
    float bv[8];
    *(float4*)&bv[0] = *(const float4*)(bias + ccol0);
    *(float4*)&bv[4] = *(const float4*)(bias + ccol0 + 4);
#pragma unroll
    for (int i = 0; i < 8; i++) {
        float4 r0, r1;
        r0.x = (acc[i][0] + bv[0]) * alpha;
        r0.y = (acc[i][1] + bv[1]) * alpha;
        r0.z = (acc[i][2] + bv[2]) * alpha;
        r0.w = (acc[i][3] + bv[3]) * alpha;
        r1.x = (acc[i][4] + bv[4]) * alpha;
        r1.y = (acc[i][5] + bv[5]) * alpha;
        r1.z = (acc[i][6] + bv[6]) * alpha;
        r1.w = (acc[i][7] + bv[7]) * alpha;
        *(float4*)(C + (size_t)(crow0 + i) * N + ccol0)     = r0;
        *(float4*)(C + (size_t)(crow0 + i) * N + ccol0 + 4) = r1;
    }
}

// ---------------------------------------------------------------------------
// Flash-style masked attention, fp32.
// Grid: (H, SEQ/128, BATCH). Block: 128 threads; thread t owns q-row qt*128+t.
// K/V tiles of 64 keys staged in smem; chunked (8-key) online softmax keeps
// scores in registers. Mask read per-thread as int4 (nonzero == masked; bit
// patterns of int32 1 and float32 1.0f are both nonzero).
// ---------------------------------------------------------------------------
__global__ void __launch_bounds__(128) attn_kernel(
    const float* __restrict__ Qp, const float* __restrict__ Kp,
    const float* __restrict__ Vp, const int* __restrict__ mask,
    float* __restrict__ ctx)
{
    __shared__ float Ks[64][68];
    __shared__ float Vs[64][68];

    const int tid = threadIdx.x;
    const int h  = blockIdx.x;
    const int qt = blockIdx.y;
    const int b  = blockIdx.z;
    const int qrow = qt * 128 + tid;

    // q row -> registers (already scaled by 1/8 in the Q projection)
    float4 q4[16];
    const float4* qg = (const float4*)(Qp + ((size_t)(b * SEQ + qrow)) * DIM + h * DPH);
#pragma unroll
    for (int i = 0; i < 16; i++) q4[i] = qg[i];

    float4 o4[16];
#pragma unroll
    for (int i = 0; i < 16; i++) o4[i] = make_float4(0.f, 0.f, 0.f, 0.f);

    float m = -1e30f, l = 0.f;
    const int* mrow = mask + ((size_t)(b * SEQ + qrow)) * SEQ;

    for (int k0 = 0; k0 < SEQ; k0 += 64) {
        __syncthreads();
        // cooperative coalesced K/V tile load: 64 rows x 16 float4
#pragma unroll
        for (int it = 0; it < 8; it++) {
            int idx = it * 128 + tid;      // 0..1023
            int row = idx >> 4;
            int c4  = idx & 15;
            size_t gofs = ((size_t)(b * SEQ + k0 + row)) * DIM + h * DPH + c4 * 4;
            *(float4*)&Ks[row][c4 * 4] = *(const float4*)(Kp + gofs);
            *(float4*)&Vs[row][c4 * 4] = *(const float4*)(Vp + gofs);
        }
        __syncthreads();

#pragma unroll 1
        for (int c = 0; c < 8; c++) {
            const int4 mk0 = *(const int4*)(mrow + k0 + c * 8);
            const int4 mk1 = *(const int4*)(mrow + k0 + c * 8 + 4);
            int mk[8] = { mk0.x, mk0.y, mk0.z, mk0.w, mk1.x, mk1.y, mk1.z, mk1.w };

            float s[8];
#pragma unroll
            for (int jj = 0; jj < 8; jj++) {
                const int j = c * 8 + jj;
                float4 a = make_float4(0.f, 0.f, 0.f, 0.f);
#pragma unroll
                for (int d4 = 0; d4 < 16; d4++) {
                    float4 kv = *(const float4*)&Ks[j][d4 * 4];
                    a.x = fmaf(q4[d4].x, kv.x, a.x);
                    a.y = fmaf(q4[d4].y, kv.y, a.y);
                    a.z = fmaf(q4[d4].z, kv.z, a.z);
                    a.w = fmaf(q4[d4].w, kv.w, a.w);
                }
                float dot = (a.x + a.y) + (a.z + a.w);
                s[jj] = mk[jj] ? -1e30f : dot;
            }

            float cm = fmaxf(fmaxf(fmaxf(s[0], s[1]), fmaxf(s[2], s[3])),
                             fmaxf(fmaxf(s[4], s[5]), fmaxf(s[6], s[7])));
            float mnew = fmaxf(m, cm);
            if (mnew > m) {           // rare after warmup
                float corr = __expf(m - mnew);
                l *= corr;
#pragma unroll
                for (int i = 0; i < 16; i++) {
                    o4[i].x *= corr; o4[i].y *= corr;
                    o4[i].z *= corr; o4[i].w *= corr;
                }
                m = mnew;
            }

            float p[8];
#pragma unroll
            for (int jj = 0; jj < 8; jj++) {
                p[jj] = mk[jj] ? 0.f : __expf(s[jj] - m);
                l += p[jj];
            }

#pragma unroll
            for (int jj = 0; jj < 8; jj++) {
                const int j = c * 8 + jj;
                const float pj = p[jj];
#pragma unroll
                for (int d4 = 0; d4 < 16; d4++) {
                    float4 vv = *(const float4*)&Vs[j][d4 * 4];
                    o4[d4].x = fmaf(pj, vv.x, o4[d4].x);
                    o4[d4].y = fmaf(pj, vv.y, o4[d4].y);
                    o4[d4].z = fmaf(pj, vv.z, o4[d4].z);
                    o4[d4].w = fmaf(pj, vv.w, o4[d4].w);
                }
            }
        }
    }

    const float inv = 1.f / l;
    float4* og = (float4*)(ctx + ((size_t)(b * SEQ + qrow)) * DIM + h * DPH);
#pragma unroll
    for (int i = 0; i < 16; i++) {
        float4 ov = o4[i];
        ov.x *= inv; ov.y *= inv; ov.z *= inv; ov.w *= inv;
        og[i] = ov;
    }
}

// ---------------------------------------------------------------------------
extern "C" void kernel_launch(void* const* d_in, const int* in_sizes, int n_in,
                              void* d_out, int out_size)
{
    (void)in_sizes; (void)n_in; (void)out_size;
    const float* key   = (const float*)d_in[0];
    const float* value = (const float*)d_in[1];
    const float* query = (const float*)d_in[2];
    const int*   mask  = (const int*)  d_in[3];
    const float* Wq = (const float*)d_in[4];
    const float* bq = (const float*)d_in[5];
    const float* Wk = (const float*)d_in[6];
    const float* bk = (const float*)d_in[7];
    const float* Wv = (const float*)d_in[8];
    const float* bv = (const float*)d_in[9];
    const float* Wo = (const float*)d_in[10];
    const float* bo = (const float*)d_in[11];
    float* out = (float*)d_out;

    float *gq, *gk, *gv, *gc;
    cudaGetSymbolAddress((void**)&gq, g_q);
    cudaGetSymbolAddress((void**)&gk, g_k);
    cudaGetSymbolAddress((void**)&gv, g_v);
    cudaGetSymbolAddress((void**)&gc, g_ctx);

    const dim3 gblk(DIM / 128, MROWS / 128);   // (8, 32)

    // Projections (q gets the 1/sqrt(DPH)=0.125 scale folded in)
    sgemm_bias<<<gblk, 256>>>(query, Wq, bq, gq, MROWS, DIM, DIM, 0.125f);
    sgemm_bias<<<gblk, 256>>>(key,   Wk, bk, gk, MROWS, DIM, DIM, 1.0f);
    sgemm_bias<<<gblk, 256>>>(value, Wv, bv, gv, MROWS, DIM, DIM, 1.0f);

    // Attention
    attn_kernel<<<dim3(HEADS, SEQ / 128, BATCH), 128>>>(gq, gk, gv, mask, gc);

    // Output projection
    sgemm_bias<<<gblk, 256>>>(gc, Wo, bo, out, MROWS, DIM, DIM, 1.0f);
}

// round 4
// speedup vs baseline: 1.1628x; 1.1628x over previous
#include <cuda_runtime.h>
#include <cuda_bf16.h>
#include <math.h>
#include <stdint.h>

// Problem constants (B=2, S=2048, D=1024, H=16, DPH=64)
#define BATCH 2
#define SEQ   2048
#define DIM   1024
#define HEADS 16
#define DPH   64
#define MROWS (BATCH * SEQ)   // 4096

typedef unsigned long long u64;

// ---------------------------------------------------------------------------
// Scratch (allocation-free rule: __device__ globals)
// ---------------------------------------------------------------------------
__device__ float g_q[BATCH * SEQ * DIM];
__device__ float g_k[BATCH * SEQ * DIM];
__device__ float g_v[BATCH * SEQ * DIM];
__device__ float g_ctx[BATCH * SEQ * DIM];
__device__ __nv_bfloat16 g_ah[MROWS * DIM];    // activation hi
__device__ __nv_bfloat16 g_al[MROWS * DIM];    // activation lo
__device__ __nv_bfloat16 g_wh[DIM * DIM];      // W^T hi  [n][k]
__device__ __nv_bfloat16 g_wl[DIM * DIM];      // W^T lo  [n][k]

// ---------------------------------------------------------------------------
// Baseline-ISA PTX helpers (no sm_103a-only features!)
// ---------------------------------------------------------------------------
__device__ __forceinline__ void cpasync16(uint32_t dst, const void* src) {
    asm volatile("cp.async.cg.shared.global [%0], [%1], 16;"
                 :: "r"(dst), "l"(src) : "memory");
}
__device__ __forceinline__ void ldsm4(uint32_t* r, uint32_t addr) {
    asm volatile("ldmatrix.sync.aligned.m8n8.x4.shared.b16 {%0,%1,%2,%3}, [%4];"
                 : "=r"(r[0]), "=r"(r[1]), "=r"(r[2]), "=r"(r[3]) : "r"(addr));
}
__device__ __forceinline__ void mma_bf16(float* c, const uint32_t* a, const uint32_t* b) {
    asm volatile("mma.sync.aligned.m16n8k16.row.col.f32.bf16.bf16.f32 "
                 "{%0,%1,%2,%3}, {%4,%5,%6,%7}, {%8,%9}, {%0,%1,%2,%3};"
                 : "+f"(c[0]), "+f"(c[1]), "+f"(c[2]), "+f"(c[3])
                 : "r"(a[0]), "r"(a[1]), "r"(a[2]), "r"(a[3]),
                   "r"(b[0]), "r"(b[1]));
}
// packed f32x2 (sm_100+ baseline)
__device__ __forceinline__ u64 ffma2(u64 a, u64 b, u64 c) {
    u64 d;
    asm("fma.rn.f32x2 %0, %1, %2, %3;" : "=l"(d) : "l"(a), "l"(b), "l"(c));
    return d;
}
__device__ __forceinline__ u64 fmul2(u64 a, u64 b) {
    u64 d;
    asm("mul.rn.f32x2 %0, %1, %2;" : "=l"(d) : "l"(a), "l"(b));
    return d;
}
__device__ __forceinline__ u64 pack2(float x) {
    u64 d;
    asm("mov.b64 %0, {%1, %1};" : "=l"(d) : "f"(x));
    return d;
}
__device__ __forceinline__ float2 unpack2(u64 v) {
    uint32_t lo, hi;
    asm("mov.b64 {%0, %1}, %2;" : "=r"(lo), "=r"(hi) : "l"(v));
    return make_float2(__uint_as_float(lo), __uint_as_float(hi));
}

// ---------------------------------------------------------------------------
// Precision-split conversion: x -> hi(bf16) + lo(bf16)
// ---------------------------------------------------------------------------
__global__ void __launch_bounds__(256) conv_act(
    const float* __restrict__ x, __nv_bfloat16* __restrict__ hi,
    __nv_bfloat16* __restrict__ lo, int n4)
{
    int i = blockIdx.x * blockDim.x + threadIdx.x;
    if (i >= n4) return;
    float4 v = ((const float4*)x)[i];
    __nv_bfloat16 h0 = __float2bfloat16(v.x);
    __nv_bfloat16 h1 = __float2bfloat16(v.y);
    __nv_bfloat16 h2 = __float2bfloat16(v.z);
    __nv_bfloat16 h3 = __float2bfloat16(v.w);
    __nv_bfloat16 l0 = __float2bfloat16(v.x - __bfloat162float(h0));
    __nv_bfloat16 l1 = __float2bfloat16(v.y - __bfloat162float(h1));
    __nv_bfloat16 l2 = __float2bfloat16(v.z - __bfloat162float(h2));
    __nv_bfloat16 l3 = __float2bfloat16(v.w - __bfloat162float(h3));
    ((__nv_bfloat162*)hi)[2 * i]     = __halves2bfloat162(h0, h1);
    ((__nv_bfloat162*)hi)[2 * i + 1] = __halves2bfloat162(h2, h3);
    ((__nv_bfloat162*)lo)[2 * i]     = __halves2bfloat162(l0, l1);
    ((__nv_bfloat162*)lo)[2 * i + 1] = __halves2bfloat162(l2, l3);
}

// W[k][n] (fp32) -> Wt_hi[n][k], Wt_lo[n][k] (bf16), tiled transpose
__global__ void __launch_bounds__(256) conv_w(
    const float* __restrict__ W, __nv_bfloat16* __restrict__ th,
    __nv_bfloat16* __restrict__ tl)
{
    __shared__ float t[32][33];
    const int n0 = blockIdx.x * 32, k0 = blockIdx.y * 32;
#pragma unroll
    for (int j = 0; j < 4; j++)
        t[threadIdx.y + j * 8][threadIdx.x] =
            W[(size_t)(k0 + threadIdx.y + j * 8) * DIM + n0 + threadIdx.x];
    __syncthreads();
#pragma unroll
    for (int j = 0; j < 4; j++) {
        float v = t[threadIdx.x][threadIdx.y + j * 8];
        __nv_bfloat16 h = __float2bfloat16(v);
        __nv_bfloat16 l = __float2bfloat16(v - __bfloat162float(h));
        size_t o = (size_t)(n0 + threadIdx.y + j * 8) * DIM + k0 + threadIdx.x;
        th[o] = h;
        tl[o] = l;
    }
}

// ---------------------------------------------------------------------------
// mma.sync bf16x3 GEMM:  C[4096,1024] = (Ah+Al) @ (Wh+Wl)^T (+bias)*alpha
// CTA tile 128x128, 8 warps (2x4), warp tile 64x32, k-step 32.
// SMEM rows are 128B: [hi 64B | lo 64B], chunk-swizzled (c ^= r&7) for
// conflict-free ldmatrix. cp.async double buffer.
// ---------------------------------------------------------------------------
#define GEMM_SMEM 65536   // 2 stages * (A 16KB + W 16KB)
#define NKSTEP (DIM / 32) // 32

__device__ __forceinline__ void gemm_load_tile(
    uint32_t smb, const char* const* srcs, int kt, int s, int tid)
{
#pragma unroll
    for (int u = 0; u < 8; u++) {
        int idx  = u * 256 + tid;        // 0..2047
        int tile = idx >> 10;            // 0=A, 1=W
        int r    = (idx >> 3) & 127;
        int c    = idx & 7;              // chunk within 128B row
        const char* src = srcs[tile * 2 + (c >> 2)]
                        + (size_t)r * 2048 + kt * 64 + (c & 3) * 16;
        uint32_t dst = smb + s * 32768 + tile * 16384
                     + r * 128 + ((c ^ (r & 7)) << 4);
        cpasync16(dst, src);
    }
}

__device__ __forceinline__ void gemm_compute_stage(
    uint32_t smb, int s, int lane, int warp_m, int warp_n, float acc[4][4][4])
{
    const uint32_t abase = smb + s * 32768;
    const uint32_t wbase = abase + 16384;
    const int kh = lane >> 4;

#pragma unroll
    for (int kb = 0; kb < 2; kb++) {
        uint32_t a_h[4][4], a_l[4][4];
#pragma unroll
        for (int i = 0; i < 4; i++) {
            int rl = warp_m * 64 + i * 16 + (lane & 15);
            int ch0 = (kb * 2 + kh) ^ (rl & 7);
            int ch1 = (4 + kb * 2 + kh) ^ (rl & 7);
            ldsm4(a_h[i], abase + rl * 128 + (ch0 << 4));
            ldsm4(a_l[i], abase + rl * 128 + (ch1 << 4));
        }
        uint32_t b_h[4][2], b_l[4][2];
#pragma unroll
        for (int j2 = 0; j2 < 2; j2++) {
            int nl = warp_n * 32 + j2 * 16 + ((lane >> 3) & 1) * 8 + (lane & 7);
            int ch0 = (kb * 2 + kh) ^ (nl & 7);
            int ch1 = (4 + kb * 2 + kh) ^ (nl & 7);
            uint32_t t[4];
            ldsm4(t, wbase + nl * 128 + (ch0 << 4));
            b_h[j2 * 2][0]     = t[0]; b_h[j2 * 2][1]     = t[2];
            b_h[j2 * 2 + 1][0] = t[1]; b_h[j2 * 2 + 1][1] = t[3];
            ldsm4(t, wbase + nl * 128 + (ch1 << 4));
            b_l[j2 * 2][0]     = t[0]; b_l[j2 * 2][1]     = t[2];
            b_l[j2 * 2 + 1][0] = t[1]; b_l[j2 * 2 + 1][1] = t[3];
        }
#pragma unroll
        for (int i = 0; i < 4; i++)
#pragma unroll
            for (int jn = 0; jn < 4; jn++) {
                mma_bf16(acc[i][jn], a_h[i], b_h[jn]);
                mma_bf16(acc[i][jn], a_h[i], b_l[jn]);
                mma_bf16(acc[i][jn], a_l[i], b_h[jn]);
            }
    }
}

__global__ void __launch_bounds__(256) gemm_mma(
    const __nv_bfloat16* __restrict__ Ah, const __nv_bfloat16* __restrict__ Al,
    const __nv_bfloat16* __restrict__ Wh, const __nv_bfloat16* __restrict__ Wl,
    const float* __restrict__ bias, float* __restrict__ C, float alpha)
{
    extern __shared__ char sm[];
    const int tid = threadIdx.x;
    const int lane = tid & 31, wid = tid >> 5;
    const int bx = blockIdx.x, by = blockIdx.y;
    const int warp_m = wid & 1, warp_n = wid >> 1;
    const uint32_t smb = (uint32_t)__cvta_generic_to_shared(sm);

    const char* srcs[4] = {
        (const char*)Ah + (size_t)by * 128 * 2048,
        (const char*)Al + (size_t)by * 128 * 2048,
        (const char*)Wh + (size_t)bx * 128 * 2048,
        (const char*)Wl + (size_t)bx * 128 * 2048
    };

    float acc[4][4][4];
#pragma unroll
    for (int i = 0; i < 4; i++)
#pragma unroll
        for (int j = 0; j < 4; j++)
#pragma unroll
            for (int r = 0; r < 4; r++) acc[i][j][r] = 0.f;

    gemm_load_tile(smb, srcs, 0, 0, tid);
    asm volatile("cp.async.commit_group;" ::: "memory");
    gemm_load_tile(smb, srcs, 1, 1, tid);
    asm volatile("cp.async.commit_group;" ::: "memory");

#pragma unroll 1
    for (int kt = 0; kt < NKSTEP; kt++) {
        asm volatile("cp.async.wait_group 1;" ::: "memory");
        __syncthreads();
        gemm_compute_stage(smb, kt & 1, lane, warp_m, warp_n, acc);
        __syncthreads();
        if (kt + 2 < NKSTEP)
            gemm_load_tile(smb, srcs, kt + 2, kt & 1, tid);
        asm volatile("cp.async.commit_group;" ::: "memory");
    }

    // epilogue
    const int r0 = lane >> 2;
    const int c0 = (lane & 3) * 2;
#pragma unroll
    for (int jn = 0; jn < 4; jn++) {
        int col = bx * 128 + warp_n * 32 + jn * 8 + c0;
        float b0 = bias[col], b1 = bias[col + 1];
#pragma unroll
        for (int i = 0; i < 4; i++) {
            int row = by * 128 + warp_m * 64 + i * 16 + r0;
            float2 v0 = make_float2((acc[i][jn][0] + b0) * alpha,
                                    (acc[i][jn][1] + b1) * alpha);
            float2 v1 = make_float2((acc[i][jn][2] + b0) * alpha,
                                    (acc[i][jn][3] + b1) * alpha);
            *(float2*)(C + (size_t)row * DIM + col)       = v0;
            *(float2*)(C + (size_t)(row + 8) * DIM + col) = v1;
        }
    }
}

// ---------------------------------------------------------------------------
// Flash-style masked attention, fp32 with packed f32x2 FMA (FFMA2).
// Grid: (H, SEQ/128, BATCH). Block: 128 threads; thread t owns one q-row.
// ---------------------------------------------------------------------------
__global__ void __launch_bounds__(128) attn_kernel(
    const float* __restrict__ Qp, const float* __restrict__ Kp,
    const float* __restrict__ Vp, const int* __restrict__ mask,
    float* __restrict__ ctx)
{
    __shared__ float Ks[64][68];
    __shared__ float Vs[64][68];

    const int tid = threadIdx.x;
    const int h  = blockIdx.x;
    const int qt = blockIdx.y;
    const int b  = blockIdx.z;
    const int qrow = qt * 128 + tid;

    // q row -> 32 packed f32x2 registers (scale 0.125 folded into Q proj)
    u64 q2[32];
    const ulonglong2* qg =
        (const ulonglong2*)(Qp + ((size_t)(b * SEQ + qrow)) * DIM + h * DPH);
#pragma unroll
    for (int i = 0; i < 16; i++) {
        ulonglong2 v = qg[i];
        q2[2 * i] = v.x; q2[2 * i + 1] = v.y;
    }

    u64 o2[32];
#pragma unroll
    for (int i = 0; i < 32; i++) o2[i] = 0ull;   // (0.0f, 0.0f)

    float m = -1e30f, l = 0.f;
    const int* mrow = mask + ((size_t)(b * SEQ + qrow)) * SEQ;

    for (int k0 = 0; k0 < SEQ; k0 += 64) {
        __syncthreads();
#pragma unroll
        for (int it = 0; it < 8; it++) {
            int idx = it * 128 + tid;
            int row = idx >> 4;
            int c4  = idx & 15;
            size_t gofs = ((size_t)(b * SEQ + k0 + row)) * DIM + h * DPH + c4 * 4;
            *(float4*)&Ks[row][c4 * 4] = *(const float4*)(Kp + gofs);
            *(float4*)&Vs[row][c4 * 4] = *(const float4*)(Vp + gofs);
        }
        __syncthreads();

#pragma unroll 1
        for (int c = 0; c < 8; c++) {
            const int4 mk0 = *(const int4*)(mrow + k0 + c * 8);
            const int4 mk1 = *(const int4*)(mrow + k0 + c * 8 + 4);
            int mk[8] = { mk0.x, mk0.y, mk0.z, mk0.w, mk1.x, mk1.y, mk1.z, mk1.w };

            float s[8];
#pragma unroll
            for (int jj = 0; jj < 8; jj++) {
                const int j = c * 8 + jj;
                const ulonglong2* kr = (const ulonglong2*)&Ks[j][0];
                u64 a0 = 0ull, a1 = 0ull;
#pragma unroll
                for (int d8 = 0; d8 < 16; d8++) {    // FIXED: full 64-dim head
                    ulonglong2 kk = kr[d8];
                    a0 = ffma2(q2[2 * d8],     kk.x, a0);
                    a1 = ffma2(q2[2 * d8 + 1], kk.y, a1);
                }
                float2 f0 = unpack2(a0), f1 = unpack2(a1);
                float dot = (f0.x + f0.y) + (f1.x + f1.y);
                s[jj] = mk[jj] ? -1e30f : dot;
            }

            float cm = fmaxf(fmaxf(fmaxf(s[0], s[1]), fmaxf(s[2], s[3])),
                             fmaxf(fmaxf(s[4], s[5]), fmaxf(s[6], s[7])));
            float mnew = fmaxf(m, cm);
            if (mnew > m) {            // rare after warmup
                float corr = __expf(m - mnew);
                u64 corr2 = pack2(corr);
                l *= corr;
#pragma unroll
                for (int i = 0; i < 32; i++) o2[i] = fmul2(corr2, o2[i]);
                m = mnew;
            }

            float p[8];
#pragma unroll
            for (int jj = 0; jj < 8; jj++) {
                p[jj] = mk[jj] ? 0.f : __expf(s[jj] - m);
                l += p[jj];
            }

#pragma unroll
            for (int jj = 0; jj < 8; jj++) {
                const int j = c * 8 + jj;
                const u64 p2 = pack2(p[jj]);
                const ulonglong2* vr = (const ulonglong2*)&Vs[j][0];
#pragma unroll
                for (int d8 = 0; d8 < 16; d8++) {    // FIXED: full 64-dim head
                    ulonglong2 vv = vr[d8];
                    o2[2 * d8]     = ffma2(p2, vv.x, o2[2 * d8]);
                    o2[2 * d8 + 1] = ffma2(p2, vv.y, o2[2 * d8 + 1]);
                }
            }
        }
    }

    const float inv = 1.f / l;
    float* og = ctx + ((size_t)(b * SEQ + qrow)) * DIM + h * DPH;
#pragma unroll
    for (int i = 0; i < 32; i++) {
        float2 v = unpack2(o2[i]);
        float2 w = make_float2(v.x * inv, v.y * inv);
        *(float2*)(og + i * 2) = w;
    }
}

// ---------------------------------------------------------------------------
extern "C" void kernel_launch(void* const* d_in, const int* in_sizes, int n_in,
                              void* d_out, int out_size)
{
    (void)in_sizes; (void)n_in; (void)out_size;
    const float* key   = (const float*)d_in[0];
    const float* value = (const float*)d_in[1];
    const float* query = (const float*)d_in[2];
    const int*   mask  = (const int*)  d_in[3];
    const float* Wq = (const float*)d_in[4];
    const float* bq = (const float*)d_in[5];
    const float* Wk = (const float*)d_in[6];
    const float* bk = (const float*)d_in[7];
    const float* Wv = (const float*)d_in[8];
    const float* bv = (const float*)d_in[9];
    const float* Wo = (const float*)d_in[10];
    const float* bo = (const float*)d_in[11];
    float* out = (float*)d_out;

    float *gq, *gk, *gv, *gc;
    __nv_bfloat16 *gah, *gal, *gwh, *gwl;
    cudaGetSymbolAddress((void**)&gq, g_q);
    cudaGetSymbolAddress((void**)&gk, g_k);
    cudaGetSymbolAddress((void**)&gv, g_v);
    cudaGetSymbolAddress((void**)&gc, g_ctx);
    cudaGetSymbolAddress((void**)&gah, g_ah);
    cudaGetSymbolAddress((void**)&gal, g_al);
    cudaGetSymbolAddress((void**)&gwh, g_wh);
    cudaGetSymbolAddress((void**)&gwl, g_wl);

    cudaFuncSetAttribute(gemm_mma,
                         cudaFuncAttributeMaxDynamicSharedMemorySize, GEMM_SMEM);

    const dim3 ggrid(DIM / 128, MROWS / 128);       // (8, 32)
    const dim3 wgrid(32, 32);
    const dim3 wblk(32, 8);
    const int n4 = MROWS * DIM / 4;

    // Q projection (1/sqrt(DPH)=0.125 folded into epilogue)
    conv_w<<<wgrid, wblk>>>(Wq, gwh, gwl);
    conv_act<<<n4 / 256, 256>>>(query, gah, gal, n4);
    gemm_mma<<<ggrid, 256, GEMM_SMEM>>>(gah, gal, gwh, gwl, bq, gq, 0.125f);

    // K projection
    conv_w<<<wgrid, wblk>>>(Wk, gwh, gwl);
    conv_act<<<n4 / 256, 256>>>(key, gah, gal, n4);
    gemm_mma<<<ggrid, 256, GEMM_SMEM>>>(gah, gal, gwh, gwl, bk, gk, 1.0f);

    // V projection
    conv_w<<<wgrid, wblk>>>(Wv, gwh, gwl);
    conv_act<<<n4 / 256, 256>>>(value, gah, gal, n4);
    gemm_mma<<<ggrid, 256, GEMM_SMEM>>>(gah, gal, gwh, gwl, bv, gv, 1.0f);

    // Attention
    attn_kernel<<<dim3(HEADS, SEQ / 128, BATCH), 128>>>(gq, gk, gv, mask, gc);

    // Output projection
    conv_w<<<wgrid, wblk>>>(Wo, gwh, gwl);
    conv_act<<<n4 / 256, 256>>>(gc, gah, gal, n4);
    gemm_mma<<<ggrid, 256, GEMM_SMEM>>>(gah, gal, gwh, gwl, bo, out, 1.0f);
}